// round 12
// baseline (speedup 1.0000x reference)
#include <cuda_runtime.h>
#include <cuda_bf16.h>
#include <cuda_fp16.h>

#define NN 50000
#define EE 800000

// ---------------- scratch (device globals; allocation-free) ----------------
// layers 1/2: z stored interleaved fp16: per row 32 chunks of 16B,
//   chunk p = { h0(2p,2p+1), h1(..), h2(..), h3(..) } as 4x half2.
// layer 3 reuses as fp32 [N,8].
__device__ float  g_z [NN * 256];
__device__ float  g_el[NN * 4];
__device__ float  g_er[NN * 4];
__device__ float  g_h [NN * 64];          // layer activations (pre-BN)
__device__ int    g_deg[NN];
__device__ int    g_rowptr[NN + 1];
__device__ int    g_cursor[NN];
__device__ int    g_csrc[EE];             // CSR-by-dst: src ids
__device__ double g_bnsum[2][64], g_bnsq[2][64];   // double-buffered per layer
__device__ float  g_scale[64], g_shift[64];

// ---------------- packed f32x2 helpers (Blackwell) ----------------
__device__ __forceinline__ unsigned long long pack2(float lo, float hi) {
    unsigned long long d;
    asm("mov.b64 %0, {%1, %2};" : "=l"(d) : "f"(lo), "f"(hi));
    return d;
}
__device__ __forceinline__ void unpack2(unsigned long long d, float& lo, float& hi) {
    asm("mov.b64 {%0, %1}, %2;" : "=f"(lo), "=f"(hi) : "l"(d));
}
__device__ __forceinline__ void ffma2(unsigned long long& d, unsigned long long a,
                                      unsigned long long b) {
    asm("fma.rn.f32x2 %0, %1, %2, %0;" : "+l"(d) : "l"(a), "l"(b));
}

// ---------------- zero pass (deg + both BN accumulator sets) ----------------
__global__ void zero_all(int* deg, int n)
{
    int i = blockIdx.x * blockDim.x + threadIdx.x;
    if (i < n) deg[i] = 0;
    if (blockIdx.x == 0 && threadIdx.x < 64) {
        g_bnsum[0][threadIdx.x] = 0.0; g_bnsq[0][threadIdx.x] = 0.0;
        g_bnsum[1][threadIdx.x] = 0.0; g_bnsq[1][threadIdx.x] = 0.0;
    }
}

// ---------------- CSR build ----------------
__global__ void count_deg(const int* __restrict__ dst, int* __restrict__ deg, int E)
{
    int i0 = (blockIdx.x * blockDim.x + threadIdx.x) * 4;
    if (i0 + 3 < E) {
        int4 d4 = *(const int4*)(dst + i0);
        atomicAdd(&deg[d4.x], 1);
        atomicAdd(&deg[d4.y], 1);
        atomicAdd(&deg[d4.z], 1);
        atomicAdd(&deg[d4.w], 1);
    } else {
        for (int i = i0; i < E; i++) atomicAdd(&deg[dst[i]], 1);
    }
}

__global__ void scan_rowptr(const int* __restrict__ deg, int* __restrict__ rowptr,
                            int* __restrict__ cursor, int n)
{
    __shared__ int ts[1024];
    int t = threadIdx.x;
    int ch = (n + 1023) >> 10;
    int beg = t * ch;
    int end = beg + ch < n ? beg + ch : n;
    int s = 0;
    for (int i = beg; i < end; i++) s += deg[i];
    ts[t] = s;
    __syncthreads();
    for (int off = 1; off < 1024; off <<= 1) {
        int v = (t >= off) ? ts[t - off] : 0;
        __syncthreads();
        ts[t] += v;
        __syncthreads();
    }
    int run = ts[t] - s;   // exclusive prefix
    for (int i = beg; i < end; i++) {
        rowptr[i] = run; cursor[i] = run; run += deg[i];
    }
    if (t == 1023) rowptr[n] = ts[1023];
}

__global__ void scatter_csr(const int* __restrict__ src, const int* __restrict__ dst,
                            int* __restrict__ cursor, int* __restrict__ csrc, int E)
{
    int i0 = (blockIdx.x * blockDim.x + threadIdx.x) * 4;
    if (i0 + 3 < E) {
        int4 d4 = *(const int4*)(dst + i0);
        int4 s4 = *(const int4*)(src + i0);
        int p0 = atomicAdd(&cursor[d4.x], 1);
        int p1 = atomicAdd(&cursor[d4.y], 1);
        int p2 = atomicAdd(&cursor[d4.z], 1);
        int p3 = atomicAdd(&cursor[d4.w], 1);
        csrc[p0] = s4.x; csrc[p1] = s4.y; csrc[p2] = s4.z; csrc[p3] = s4.w;
    } else {
        for (int i = i0; i < E; i++) {
            int pos = atomicAdd(&cursor[dst[i]], 1);
            csrc[pos] = src[i];
        }
    }
}

// ---------------- GEMM (Nout=256, interleaved fp16 z) + fused el/er, optional BN ----------------
// block 256 threads, 32 rows/block. thread t: cols 4*(t&63), rows (t>>6)*8 .. +7 (4 pairs)
template<int KIN, bool APPLY_BN>
__global__ void gemm_attn(const float* __restrict__ x, const float* __restrict__ W,
                          const float* __restrict__ al, const float* __restrict__ ar,
                          unsigned int* __restrict__ z, float* __restrict__ el,
                          float* __restrict__ er, int n)
{
    __shared__ __align__(16) float xs[KIN][34];   // k-major; pad 34 (even) for banks+align
    int t = threadIdx.x;
    int base = blockIdx.x * 32;
    for (int idx = t; idx < 32 * KIN; idx += 256) {
        int r = idx / KIN, k = idx - r * KIN;     // coalesced read along k
        int row = base + r;
        float v = (row < n) ? x[(size_t)row * KIN + k] : 0.f;
        if (APPLY_BN) v = v * g_scale[k] + g_shift[k];
        xs[k][r] = v;
    }
    __syncthreads();
    int c4 = t & 63, rr = t >> 6;
    const float4* W4 = (const float4*)W;
    unsigned long long acc[4][4];
    #pragma unroll
    for (int rp = 0; rp < 4; rp++)
        #pragma unroll
        for (int c = 0; c < 4; c++) acc[rp][c] = 0ull;
    for (int k = 0; k < KIN; k++) {
        float4 w = W4[k * 64 + c4];
        unsigned long long wd0 = pack2(w.x, w.x), wd1 = pack2(w.y, w.y),
                           wd2 = pack2(w.z, w.z), wd3 = pack2(w.w, w.w);
        const unsigned long long* xp = (const unsigned long long*)(&xs[k][rr * 8]);
        #pragma unroll
        for (int rp = 0; rp < 4; rp++) {
            unsigned long long xv = xp[rp];       // rows (rr*8+2rp, +1) packed
            ffma2(acc[rp][0], xv, wd0);
            ffma2(acc[rp][1], xv, wd1);
            ffma2(acc[rp][2], xv, wd2);
            ffma2(acc[rp][3], xv, wd3);
        }
    }
    // interleaved store coords: head h = c4>>4, dim-pair p0 = (c4&15)*2
    int hidx = c4 >> 4;
    int p0   = (c4 & 15) * 2;
    float4 alv = ((const float4*)al)[c4];
    float4 arv = ((const float4*)ar)[c4];
    #pragma unroll
    for (int rp = 0; rp < 4; rp++) {
        float v0[4], v1[4];
        unpack2(acc[rp][0], v0[0], v1[0]);
        unpack2(acc[rp][1], v0[1], v1[1]);
        unpack2(acc[rp][2], v0[2], v1[2]);
        unpack2(acc[rp][3], v0[3], v1[3]);
        #pragma unroll
        for (int half = 0; half < 2; half++) {
            float* vv = half ? v1 : v0;
            int row = base + rr * 8 + rp * 2 + half;
            if (row < n) {
                __half2 ha = __floats2half2_rn(vv[0], vv[1]);
                __half2 hb = __floats2half2_rn(vv[2], vv[3]);
                unsigned int* zp = z + ((size_t)row * 32 + p0) * 4 + hidx;
                zp[0] = *(unsigned int*)&ha;
                zp[4] = *(unsigned int*)&hb;
            }
            float p = vv[0]*alv.x + vv[1]*alv.y + vv[2]*alv.z + vv[3]*alv.w;
            float q = vv[0]*arv.x + vv[1]*arv.y + vv[2]*arv.z + vv[3]*arv.w;
            #pragma unroll
            for (int off = 8; off; off >>= 1) {
                p += __shfl_xor_sync(0xffffffffu, p, off);
                q += __shfl_xor_sync(0xffffffffu, q, off);
            }
            if ((c4 & 15) == 0 && row < n) {
                el[row * 4 + (c4 >> 4)] = p;
                er[row * 4 + (c4 >> 4)] = q;
            }
        }
    }
}

// ---------------- GEMM (Nout=8, layer 3, fp32 z) + fused el/er + fused BN ----------------
__global__ void gemm8_attn(const float* __restrict__ x, const float* __restrict__ W,
                           const float* __restrict__ al, const float* __restrict__ ar,
                           float* __restrict__ z, float* __restrict__ el,
                           float* __restrict__ er, int n)
{
    __shared__ float xs[32][64];
    __shared__ float ws[512];
    int t = threadIdx.x;
    int base = blockIdx.x * 32;
    for (int idx = t; idx < 512; idx += 256) ws[idx] = W[idx];
    for (int idx = t; idx < 2048; idx += 256) {
        int r = idx >> 6, k = idx & 63;
        int row = base + r;
        float v = (row < n) ? x[(size_t)row * 64 + k] : 0.f;
        xs[r][k] = v * g_scale[k] + g_shift[k];
    }
    __syncthreads();
    int nl = t >> 3, j = t & 7;
    int row = base + nl;
    float acc = 0.f;
    #pragma unroll
    for (int k = 0; k < 64; k++) acc += xs[nl][k] * ws[k * 8 + j];
    float p = acc * al[j], q = acc * ar[j];
    float p2 = p + __shfl_xor_sync(0xffffffffu, p, 1);
    float q2 = q + __shfl_xor_sync(0xffffffffu, q, 1);
    if (row < n) {
        z[(size_t)row * 8 + j] = acc;
        if ((j & 1) == 0) { el[row * 4 + (j >> 1)] = p2; er[row * 4 + (j >> 1)] = q2; }
    }
}

// ---------------- fused GAT aggregate (D=64, interleaved fp16 z): warp per dst ----------------
__global__ void gat_agg64(const float* __restrict__ el, const float* __restrict__ er,
                          const uint4* __restrict__ z, const int* __restrict__ rowptr,
                          const int* __restrict__ csrc, const float* __restrict__ b,
                          float* __restrict__ out, int n)
{
    int w = (blockIdx.x * blockDim.x + threadIdx.x) >> 5;
    int lane = threadIdx.x & 31;
    if (w >= n) return;
    int beg = rowptr[w], end = rowptr[w + 1];
    float4 erv = ((const float4*)er)[w];
    float num[4][2] = {};
    float den[4] = {};
    int d0 = lane * 2;
    for (int c = beg; c < end; c += 32) {
        int idx = c + lane;
        float a0 = 0.f, a1 = 0.f, a2 = 0.f, a3 = 0.f;
        int ss = 0;
        if (idx < end) {
            ss = csrc[idx];
            float4 l = ((const float4*)el)[ss];
            float e0 = l.x + erv.x, e1 = l.y + erv.y;
            float e2 = l.z + erv.z, e3 = l.w + erv.w;
            e0 = e0 > 0.f ? e0 : 0.2f * e0;
            e1 = e1 > 0.f ? e1 : 0.2f * e1;
            e2 = e2 > 0.f ? e2 : 0.2f * e2;
            e3 = e3 > 0.f ? e3 : 0.2f * e3;
            a0 = __expf(e0); a1 = __expf(e1); a2 = __expf(e2); a3 = __expf(e3);
            den[0] += a0; den[1] += a1; den[2] += a2; den[3] += a3;
        }
        int m = end - c; if (m > 32) m = 32;
        #pragma unroll 4
        for (int j = 0; j < m; j++) {
            int   sj = __shfl_sync(0xffffffffu, ss, j);
            float b0 = __shfl_sync(0xffffffffu, a0, j);
            float b1 = __shfl_sync(0xffffffffu, a1, j);
            float b2 = __shfl_sync(0xffffffffu, a2, j);
            float b3 = __shfl_sync(0xffffffffu, a3, j);
            uint4 qv = z[(size_t)sj * 32 + lane];   // all 4 heads, dims (2lane,2lane+1)
            float2 z0 = __half22float2(*(__half2*)&qv.x);
            float2 z1 = __half22float2(*(__half2*)&qv.y);
            float2 z2 = __half22float2(*(__half2*)&qv.z);
            float2 z3 = __half22float2(*(__half2*)&qv.w);
            num[0][0] += b0 * z0.x; num[0][1] += b0 * z0.y;
            num[1][0] += b1 * z1.x; num[1][1] += b1 * z1.y;
            num[2][0] += b2 * z2.x; num[2][1] += b2 * z2.y;
            num[3][0] += b3 * z3.x; num[3][1] += b3 * z3.y;
        }
    }
    #pragma unroll
    for (int off = 16; off; off >>= 1) {
        den[0] += __shfl_xor_sync(0xffffffffu, den[0], off);
        den[1] += __shfl_xor_sync(0xffffffffu, den[1], off);
        den[2] += __shfl_xor_sync(0xffffffffu, den[2], off);
        den[3] += __shfl_xor_sync(0xffffffffu, den[3], off);
    }
    // self-loop (computed identically on all lanes, added once after reduction)
    {
        float4 l = ((const float4*)el)[w];
        float e0 = l.x + erv.x, e1 = l.y + erv.y;
        float e2 = l.z + erv.z, e3 = l.w + erv.w;
        e0 = e0 > 0.f ? e0 : 0.2f * e0;
        e1 = e1 > 0.f ? e1 : 0.2f * e1;
        e2 = e2 > 0.f ? e2 : 0.2f * e2;
        e3 = e3 > 0.f ? e3 : 0.2f * e3;
        float s0 = __expf(e0), s1 = __expf(e1), s2 = __expf(e2), s3 = __expf(e3);
        den[0] += s0; den[1] += s1; den[2] += s2; den[3] += s3;
        uint4 qv = z[(size_t)w * 32 + lane];
        float2 q0 = __half22float2(*(__half2*)&qv.x);
        float2 q1 = __half22float2(*(__half2*)&qv.y);
        float2 q2 = __half22float2(*(__half2*)&qv.z);
        float2 q3 = __half22float2(*(__half2*)&qv.w);
        num[0][0] += s0 * q0.x; num[0][1] += s0 * q0.y;
        num[1][0] += s1 * q1.x; num[1][1] += s1 * q1.y;
        num[2][0] += s2 * q2.x; num[2][1] += s2 * q2.y;
        num[3][0] += s3 * q3.x; num[3][1] += s3 * q3.y;
    }
    float r0 = __fdividef(1.f, den[0]);
    float r1 = __fdividef(1.f, den[1]);
    float r2 = __fdividef(1.f, den[2]);
    float r3 = __fdividef(1.f, den[3]);
    float bx = b[d0] + b[64 + d0] + b[128 + d0] + b[192 + d0];
    float by = b[d0 + 1] + b[65 + d0] + b[129 + d0] + b[193 + d0];
    float2 o;
    o.x = bx + num[0][0]*r0 + num[1][0]*r1 + num[2][0]*r2 + num[3][0]*r3;
    o.y = by + num[0][1]*r0 + num[1][1]*r1 + num[2][1]*r2 + num[3][1]*r3;
    ((float2*)out)[(size_t)w * 32 + lane] = o;
}

// ---------------- fused GAT aggregate (C=2, layer 3, fp32 z): warp per dst node ----------------
__global__ void gat_agg2(const float* __restrict__ el, const float* __restrict__ er,
                         const float* __restrict__ z8, const int* __restrict__ rowptr,
                         const int* __restrict__ csrc, const float* __restrict__ b,
                         float* __restrict__ out, int n)
{
    int w = (blockIdx.x * blockDim.x + threadIdx.x) >> 5;
    int lane = threadIdx.x & 31;
    if (w >= n) return;
    int beg = rowptr[w], end = rowptr[w + 1];
    float4 erv = ((const float4*)er)[w];
    float num[4][2] = {};
    float den[4] = {};
    for (int idx = beg + lane; idx < end; idx += 32) {
        int ss = csrc[idx];
        float4 l = ((const float4*)el)[ss];
        float e0 = l.x + erv.x, e1 = l.y + erv.y;
        float e2 = l.z + erv.z, e3 = l.w + erv.w;
        e0 = e0 > 0.f ? e0 : 0.2f * e0;
        e1 = e1 > 0.f ? e1 : 0.2f * e1;
        e2 = e2 > 0.f ? e2 : 0.2f * e2;
        e3 = e3 > 0.f ? e3 : 0.2f * e3;
        float a0 = __expf(e0), a1 = __expf(e1), a2 = __expf(e2), a3 = __expf(e3);
        den[0] += a0; den[1] += a1; den[2] += a2; den[3] += a3;
        float4 za = ((const float4*)z8)[(size_t)ss * 2];
        float4 zb = ((const float4*)z8)[(size_t)ss * 2 + 1];
        num[0][0] += a0 * za.x; num[0][1] += a0 * za.y;
        num[1][0] += a1 * za.z; num[1][1] += a1 * za.w;
        num[2][0] += a2 * zb.x; num[2][1] += a2 * zb.y;
        num[3][0] += a3 * zb.z; num[3][1] += a3 * zb.w;
    }
    #pragma unroll
    for (int off = 16; off; off >>= 1) {
        #pragma unroll
        for (int h = 0; h < 4; h++) {
            den[h]    += __shfl_xor_sync(0xffffffffu, den[h], off);
            num[h][0] += __shfl_xor_sync(0xffffffffu, num[h][0], off);
            num[h][1] += __shfl_xor_sync(0xffffffffu, num[h][1], off);
        }
    }
    if (lane == 0) {
        float4 l = ((const float4*)el)[w];
        float e0 = l.x + erv.x, e1 = l.y + erv.y;
        float e2 = l.z + erv.z, e3 = l.w + erv.w;
        e0 = e0 > 0.f ? e0 : 0.2f * e0;
        e1 = e1 > 0.f ? e1 : 0.2f * e1;
        e2 = e2 > 0.f ? e2 : 0.2f * e2;
        e3 = e3 > 0.f ? e3 : 0.2f * e3;
        float s0 = __expf(e0), s1 = __expf(e1), s2 = __expf(e2), s3 = __expf(e3);
        den[0] += s0; den[1] += s1; den[2] += s2; den[3] += s3;
        float4 za = ((const float4*)z8)[(size_t)w * 2];
        float4 zb = ((const float4*)z8)[(size_t)w * 2 + 1];
        num[0][0] += s0 * za.x; num[0][1] += s0 * za.y;
        num[1][0] += s1 * za.z; num[1][1] += s1 * za.w;
        num[2][0] += s2 * zb.x; num[2][1] += s2 * zb.y;
        num[3][0] += s3 * zb.z; num[3][1] += s3 * zb.w;
        float o0 = b[0] + b[2] + b[4] + b[6];
        float o1 = b[1] + b[3] + b[5] + b[7];
        o0 += num[0][0]/den[0] + num[1][0]/den[1] + num[2][0]/den[2] + num[3][0]/den[3];
        o1 += num[0][1]/den[0] + num[1][1]/den[1] + num[2][1]/den[2] + num[3][1]/den[3];
        ((float2*)out)[w] = make_float2(o0, o1);
    }
}

// ---------------- batchnorm stats ----------------
template<int SET>
__global__ void bn_stats(const float* __restrict__ h, int n)
{
    int t = threadIdx.x;
    int d = t & 63, rsub = t >> 6;
    float sum = 0.f, sq = 0.f;
    for (int row = blockIdx.x * 4 + rsub; row < n; row += gridDim.x * 4) {
        float v = h[(size_t)row * 64 + d];
        sum += v; sq += v * v;
    }
    __shared__ float sh[256], shq[256];
    sh[t] = sum; shq[t] = sq;
    __syncthreads();
    if (t < 64) {
        float s4 = sh[t] + sh[t + 64] + sh[t + 128] + sh[t + 192];
        float q4 = shq[t] + shq[t + 64] + shq[t + 128] + shq[t + 192];
        atomicAdd(&g_bnsum[SET][t], (double)s4);
        atomicAdd(&g_bnsq[SET][t], (double)q4);
    }
}

template<int SET>
__global__ void bn_final(const float* __restrict__ gamma, const float* __restrict__ beta, int n)
{
    int t = threadIdx.x;
    if (t >= 64) return;
    double mean = g_bnsum[SET][t] / n;
    double var  = g_bnsq[SET][t] / n - mean * mean;
    float sc = gamma[t] * rsqrtf((float)var + 1e-5f);
    g_scale[t] = sc;
    g_shift[t] = beta[t] - (float)mean * sc;
}

// ---------------- launch ----------------
extern "C" void kernel_launch(void* const* d_in, const int* in_sizes, int n_in,
                              void* d_out, int out_size)
{
    const float* feats = (const float*)d_in[0];
    const float* W1    = (const float*)d_in[1];
    const float* al1   = (const float*)d_in[2];
    const float* ar1   = (const float*)d_in[3];
    const float* b1    = (const float*)d_in[4];
    const float* Wm    = (const float*)d_in[5];
    const float* alm   = (const float*)d_in[6];
    const float* arm   = (const float*)d_in[7];
    const float* bm    = (const float*)d_in[8];
    const float* W2    = (const float*)d_in[9];
    const float* al2   = (const float*)d_in[10];
    const float* ar2   = (const float*)d_in[11];
    const float* b2    = (const float*)d_in[12];
    const float* gamma = (const float*)d_in[13];
    const float* beta  = (const float*)d_in[14];
    const int*   src   = (const int*)d_in[15];
    const int*   dst   = (const int*)d_in[16];
    float* out = (float*)d_out;

    int n = in_sizes[0] / 9;
    int E = in_sizes[15];

    void* p;
    float *z, *el, *er, *h;
    int *deg, *rowptr, *cursor, *csrc;
    cudaGetSymbolAddress(&p, g_z);      z      = (float*)p;
    cudaGetSymbolAddress(&p, g_el);     el     = (float*)p;
    cudaGetSymbolAddress(&p, g_er);     er     = (float*)p;
    cudaGetSymbolAddress(&p, g_h);      h      = (float*)p;
    cudaGetSymbolAddress(&p, g_deg);    deg    = (int*)p;
    cudaGetSymbolAddress(&p, g_rowptr); rowptr = (int*)p;
    cudaGetSymbolAddress(&p, g_cursor); cursor = (int*)p;
    cudaGetSymbolAddress(&p, g_csrc);   csrc   = (int*)p;
    unsigned int* zu = (unsigned int*)z;
    uint4* z4 = (uint4*)z;

    int gblk = (n + 31) / 32;   // gemm blocks (32 rows each)
    int ablk = (n + 7) / 8;     // aggregate blocks (8 warps each)
    int e4blk = (E / 4 + 256) / 256;

    // ---- CSR build (reused by all 3 layers) + zero BN accumulators ----
    zero_all<<<(n + 255) / 256, 256>>>(deg, n);
    count_deg<<<e4blk, 256>>>(dst, deg, E);
    scan_rowptr<<<1, 1024>>>(deg, rowptr, cursor, n);
    scatter_csr<<<e4blk, 256>>>(src, dst, cursor, csrc, E);

    // ---- Layer 1: feats[N,9] -> h[N,64] ----
    gemm_attn<9, false><<<gblk, 256>>>(feats, W1, al1, ar1, zu, el, er, n);
    gat_agg64<<<ablk, 256>>>(el, er, z4, rowptr, csrc, b1, h, n);
    bn_stats<0><<<128, 256>>>(h, n);
    bn_final<0><<<1, 64>>>(gamma, beta, n);

    // ---- Layer 2: bn(h) -> h[N,64]  (BN folded into gemm input load) ----
    gemm_attn<64, true><<<gblk, 256>>>(h, Wm, alm, arm, zu, el, er, n);
    gat_agg64<<<ablk, 256>>>(el, er, z4, rowptr, csrc, bm, h, n);
    bn_stats<1><<<128, 256>>>(h, n);
    bn_final<1><<<1, 64>>>(gamma, beta, n);

    // ---- Layer 3: bn(h) -> out[N,2] ----
    gemm8_attn<<<gblk, 256>>>(h, W2, al2, ar2, z, el, er, n);
    gat_agg2<<<ablk, 256>>>(el, er, z, rowptr, csrc, b2, out, n);
}

// round 13
// speedup vs baseline: 1.6108x; 1.6108x over previous
#include <cuda_runtime.h>
#include <cuda_bf16.h>
#include <cuda_fp16.h>

#define NN 50000
#define EE 800000

// ---------------- scratch (device globals; allocation-free) ----------------
// layers 1/2: z fp16 [N][H][D] contiguous per row (512B/row). layer 3: fp32 [N,8].
__device__ float  g_z [NN * 256];
__device__ float  g_el[NN * 4];
__device__ float  g_er[NN * 4];
__device__ float  g_h [NN * 64];          // layer activations (pre-BN)
__device__ int    g_deg[NN];
__device__ int    g_rowptr[NN + 1];
__device__ int    g_cursor[NN];
__device__ int    g_csrc[EE];             // CSR-by-dst: src ids
__device__ double g_bnsum[2][64], g_bnsq[2][64];   // double-buffered per layer
__device__ float  g_scale[64], g_shift[64];

// ---------------- packed f32x2 helpers (Blackwell) ----------------
__device__ __forceinline__ unsigned long long pack2(float lo, float hi) {
    unsigned long long d;
    asm("mov.b64 %0, {%1, %2};" : "=l"(d) : "f"(lo), "f"(hi));
    return d;
}
__device__ __forceinline__ void unpack2(unsigned long long d, float& lo, float& hi) {
    asm("mov.b64 {%0, %1}, %2;" : "=f"(lo), "=f"(hi) : "l"(d));
}
__device__ __forceinline__ void ffma2(unsigned long long& d, unsigned long long a,
                                      unsigned long long b) {
    asm("fma.rn.f32x2 %0, %1, %2, %0;" : "+l"(d) : "l"(a), "l"(b));
}

// ---------------- zero pass (deg + both BN accumulator sets) ----------------
__global__ void zero_all(int* deg, int n)
{
    int i = blockIdx.x * blockDim.x + threadIdx.x;
    if (i < n) deg[i] = 0;
    if (blockIdx.x == 0 && threadIdx.x < 64) {
        g_bnsum[0][threadIdx.x] = 0.0; g_bnsq[0][threadIdx.x] = 0.0;
        g_bnsum[1][threadIdx.x] = 0.0; g_bnsq[1][threadIdx.x] = 0.0;
    }
}

// ---------------- CSR build ----------------
__global__ void count_deg(const int* __restrict__ dst, int* __restrict__ deg, int E)
{
    int i0 = (blockIdx.x * blockDim.x + threadIdx.x) * 4;
    if (i0 + 3 < E) {
        int4 d4 = *(const int4*)(dst + i0);
        atomicAdd(&deg[d4.x], 1);
        atomicAdd(&deg[d4.y], 1);
        atomicAdd(&deg[d4.z], 1);
        atomicAdd(&deg[d4.w], 1);
    } else {
        for (int i = i0; i < E; i++) atomicAdd(&deg[dst[i]], 1);
    }
}

__global__ void scan_rowptr(const int* __restrict__ deg, int* __restrict__ rowptr,
                            int* __restrict__ cursor, int n)
{
    __shared__ int ts[1024];
    int t = threadIdx.x;
    int ch = (n + 1023) >> 10;
    int beg = t * ch;
    int end = beg + ch < n ? beg + ch : n;
    int s = 0;
    for (int i = beg; i < end; i++) s += deg[i];
    ts[t] = s;
    __syncthreads();
    for (int off = 1; off < 1024; off <<= 1) {
        int v = (t >= off) ? ts[t - off] : 0;
        __syncthreads();
        ts[t] += v;
        __syncthreads();
    }
    int run = ts[t] - s;   // exclusive prefix
    for (int i = beg; i < end; i++) {
        rowptr[i] = run; cursor[i] = run; run += deg[i];
    }
    if (t == 1023) rowptr[n] = ts[1023];
}

__global__ void scatter_csr(const int* __restrict__ src, const int* __restrict__ dst,
                            int* __restrict__ cursor, int* __restrict__ csrc, int E)
{
    int i0 = (blockIdx.x * blockDim.x + threadIdx.x) * 4;
    if (i0 + 3 < E) {
        int4 d4 = *(const int4*)(dst + i0);
        int4 s4 = *(const int4*)(src + i0);
        int p0 = atomicAdd(&cursor[d4.x], 1);
        int p1 = atomicAdd(&cursor[d4.y], 1);
        int p2 = atomicAdd(&cursor[d4.z], 1);
        int p3 = atomicAdd(&cursor[d4.w], 1);
        csrc[p0] = s4.x; csrc[p1] = s4.y; csrc[p2] = s4.z; csrc[p3] = s4.w;
    } else {
        for (int i = i0; i < E; i++) {
            int pos = atomicAdd(&cursor[dst[i]], 1);
            csrc[pos] = src[i];
        }
    }
}

// ---------------- GEMM (Nout=256, fp16 z out) + fused el/er, optional fused BN ----------------
// block = 256 threads, 32 rows/block; thread t: cols 4*(t&63), rows (t>>6)*8 .. +7 (4 pairs)
template<int KIN, bool APPLY_BN>
__global__ void gemm_attn(const float* __restrict__ x, const float* __restrict__ W,
                          const float* __restrict__ al, const float* __restrict__ ar,
                          __half2* __restrict__ z, float* __restrict__ el,
                          float* __restrict__ er, int n)
{
    __shared__ __align__(16) float xs[KIN][34];   // k-major; pad 34 (even) for banks+align
    int t = threadIdx.x;
    int base = blockIdx.x * 32;
    for (int idx = t; idx < 32 * KIN; idx += 256) {
        int r = idx / KIN, k = idx - r * KIN;     // coalesced read along k
        int row = base + r;
        float v = (row < n) ? x[(size_t)row * KIN + k] : 0.f;
        if (APPLY_BN) v = v * g_scale[k] + g_shift[k];
        xs[k][r] = v;
    }
    __syncthreads();
    int c4 = t & 63, rr = t >> 6;
    const float4* W4 = (const float4*)W;
    unsigned long long acc[4][4];
    #pragma unroll
    for (int rp = 0; rp < 4; rp++)
        #pragma unroll
        for (int c = 0; c < 4; c++) acc[rp][c] = 0ull;
    for (int k = 0; k < KIN; k++) {
        float4 w = W4[k * 64 + c4];
        unsigned long long wd0 = pack2(w.x, w.x), wd1 = pack2(w.y, w.y),
                           wd2 = pack2(w.z, w.z), wd3 = pack2(w.w, w.w);
        const unsigned long long* xp = (const unsigned long long*)(&xs[k][rr * 8]);
        #pragma unroll
        for (int rp = 0; rp < 4; rp++) {
            unsigned long long xv = xp[rp];       // rows (rr*8+2rp, +1) packed
            ffma2(acc[rp][0], xv, wd0);
            ffma2(acc[rp][1], xv, wd1);
            ffma2(acc[rp][2], xv, wd2);
            ffma2(acc[rp][3], xv, wd3);
        }
    }
    float4 alv = ((const float4*)al)[c4];
    float4 arv = ((const float4*)ar)[c4];
    #pragma unroll
    for (int rp = 0; rp < 4; rp++) {
        float v0[4], v1[4];
        unpack2(acc[rp][0], v0[0], v1[0]);
        unpack2(acc[rp][1], v0[1], v1[1]);
        unpack2(acc[rp][2], v0[2], v1[2]);
        unpack2(acc[rp][3], v0[3], v1[3]);
        #pragma unroll
        for (int half = 0; half < 2; half++) {
            float* vv = half ? v1 : v0;
            int row = base + rr * 8 + rp * 2 + half;
            if (row < n) {
                __half2 ha = __floats2half2_rn(vv[0], vv[1]);
                __half2 hb = __floats2half2_rn(vv[2], vv[3]);
                __half2* zp = z + (size_t)row * 128 + c4 * 2;   // coalesced 8B/thread
                zp[0] = ha; zp[1] = hb;
            }
            float p = vv[0]*alv.x + vv[1]*alv.y + vv[2]*alv.z + vv[3]*alv.w;
            float q = vv[0]*arv.x + vv[1]*arv.y + vv[2]*arv.z + vv[3]*arv.w;
            #pragma unroll
            for (int off = 8; off; off >>= 1) {
                p += __shfl_xor_sync(0xffffffffu, p, off);
                q += __shfl_xor_sync(0xffffffffu, q, off);
            }
            if ((c4 & 15) == 0 && row < n) {
                el[row * 4 + (c4 >> 4)] = p;
                er[row * 4 + (c4 >> 4)] = q;
            }
        }
    }
}

// ---------------- GEMM (Nout=8, layer 3, fp32 z) + fused el/er + fused BN ----------------
__global__ void gemm8_attn(const float* __restrict__ x, const float* __restrict__ W,
                           const float* __restrict__ al, const float* __restrict__ ar,
                           float* __restrict__ z, float* __restrict__ el,
                           float* __restrict__ er, int n)
{
    __shared__ float xs[32][64];
    __shared__ float ws[512];
    int t = threadIdx.x;
    int base = blockIdx.x * 32;
    for (int idx = t; idx < 512; idx += 256) ws[idx] = W[idx];
    for (int idx = t; idx < 2048; idx += 256) {
        int r = idx >> 6, k = idx & 63;
        int row = base + r;
        float v = (row < n) ? x[(size_t)row * 64 + k] : 0.f;
        xs[r][k] = v * g_scale[k] + g_shift[k];
    }
    __syncthreads();
    int nl = t >> 3, j = t & 7;
    int row = base + nl;
    float acc = 0.f;
    #pragma unroll
    for (int k = 0; k < 64; k++) acc += xs[nl][k] * ws[k * 8 + j];
    float p = acc * al[j], q = acc * ar[j];
    float p2 = p + __shfl_xor_sync(0xffffffffu, p, 1);
    float q2 = q + __shfl_xor_sync(0xffffffffu, q, 1);
    if (row < n) {
        z[(size_t)row * 8 + j] = acc;
        if ((j & 1) == 0) { el[row * 4 + (j >> 1)] = p2; er[row * 4 + (j >> 1)] = q2; }
    }
}

// ---------------- fused GAT aggregate (D=64, fp16 z): warp per dst node ----------------
// per-chunk (ss, a0..a3) broadcast via shared memory instead of 5 dynamic shuffles/edge
__global__ void gat_agg64(const float* __restrict__ el, const float* __restrict__ er,
                          const __half2* __restrict__ z, const int* __restrict__ rowptr,
                          const int* __restrict__ csrc, const float* __restrict__ b,
                          float* __restrict__ out, int n)
{
    __shared__ __align__(16) float4 sa[8][32];
    __shared__ int sid[8][32];
    int w = (blockIdx.x * blockDim.x + threadIdx.x) >> 5;
    int wslot = (threadIdx.x >> 5) & 7;
    int lane = threadIdx.x & 31;
    if (w >= n) return;
    int beg = rowptr[w], end = rowptr[w + 1];
    float4 erv = ((const float4*)er)[w];
    float num[4][2] = {};
    float den[4] = {};
    int d0 = lane * 2;
    for (int c = beg; c < end; c += 32) {
        int idx = c + lane;
        float a0 = 0.f, a1 = 0.f, a2 = 0.f, a3 = 0.f;
        int ss = 0;
        if (idx < end) {
            ss = csrc[idx];
            float4 l = ((const float4*)el)[ss];
            float e0 = l.x + erv.x, e1 = l.y + erv.y;
            float e2 = l.z + erv.z, e3 = l.w + erv.w;
            e0 = e0 > 0.f ? e0 : 0.2f * e0;
            e1 = e1 > 0.f ? e1 : 0.2f * e1;
            e2 = e2 > 0.f ? e2 : 0.2f * e2;
            e3 = e3 > 0.f ? e3 : 0.2f * e3;
            a0 = __expf(e0); a1 = __expf(e1); a2 = __expf(e2); a3 = __expf(e3);
            den[0] += a0; den[1] += a1; den[2] += a2; den[3] += a3;
        }
        sa[wslot][lane] = make_float4(a0, a1, a2, a3);
        sid[wslot][lane] = ss;
        __syncwarp();
        int m = end - c; if (m > 32) m = 32;
        for (int j = 0; j < m; j++) {
            float4 av = sa[wslot][j];           // broadcast LDS.128 (conflict-free)
            int    sj = sid[wslot][j];          // broadcast LDS.32
            const __half2* zp = z + (size_t)sj * 128 + lane;
            float2 z0 = __half22float2(zp[0]);
            float2 z1 = __half22float2(zp[32]);
            float2 z2 = __half22float2(zp[64]);
            float2 z3 = __half22float2(zp[96]);
            num[0][0] += av.x * z0.x; num[0][1] += av.x * z0.y;
            num[1][0] += av.y * z1.x; num[1][1] += av.y * z1.y;
            num[2][0] += av.z * z2.x; num[2][1] += av.z * z2.y;
            num[3][0] += av.w * z3.x; num[3][1] += av.w * z3.y;
        }
        __syncwarp();
    }
    #pragma unroll
    for (int off = 16; off; off >>= 1) {
        den[0] += __shfl_xor_sync(0xffffffffu, den[0], off);
        den[1] += __shfl_xor_sync(0xffffffffu, den[1], off);
        den[2] += __shfl_xor_sync(0xffffffffu, den[2], off);
        den[3] += __shfl_xor_sync(0xffffffffu, den[3], off);
    }
    // self-loop (computed identically on all lanes, added once after reduction)
    {
        float4 l = ((const float4*)el)[w];
        float e0 = l.x + erv.x, e1 = l.y + erv.y;
        float e2 = l.z + erv.z, e3 = l.w + erv.w;
        e0 = e0 > 0.f ? e0 : 0.2f * e0;
        e1 = e1 > 0.f ? e1 : 0.2f * e1;
        e2 = e2 > 0.f ? e2 : 0.2f * e2;
        e3 = e3 > 0.f ? e3 : 0.2f * e3;
        float s0 = __expf(e0), s1 = __expf(e1), s2 = __expf(e2), s3 = __expf(e3);
        den[0] += s0; den[1] += s1; den[2] += s2; den[3] += s3;
        const __half2* zq = z + (size_t)w * 128 + lane;
        float2 q0 = __half22float2(zq[0]);
        float2 q1 = __half22float2(zq[32]);
        float2 q2 = __half22float2(zq[64]);
        float2 q3 = __half22float2(zq[96]);
        num[0][0] += s0 * q0.x; num[0][1] += s0 * q0.y;
        num[1][0] += s1 * q1.x; num[1][1] += s1 * q1.y;
        num[2][0] += s2 * q2.x; num[2][1] += s2 * q2.y;
        num[3][0] += s3 * q3.x; num[3][1] += s3 * q3.y;
    }
    float r0 = __fdividef(1.f, den[0]);
    float r1 = __fdividef(1.f, den[1]);
    float r2 = __fdividef(1.f, den[2]);
    float r3 = __fdividef(1.f, den[3]);
    float bx = b[d0] + b[64 + d0] + b[128 + d0] + b[192 + d0];
    float by = b[d0 + 1] + b[65 + d0] + b[129 + d0] + b[193 + d0];
    float2 o;
    o.x = bx + num[0][0]*r0 + num[1][0]*r1 + num[2][0]*r2 + num[3][0]*r3;
    o.y = by + num[0][1]*r0 + num[1][1]*r1 + num[2][1]*r2 + num[3][1]*r3;
    ((float2*)out)[(size_t)w * 32 + lane] = o;
}

// ---------------- fused GAT aggregate (C=2, layer 3, fp32 z): warp per dst node ----------------
__global__ void gat_agg2(const float* __restrict__ el, const float* __restrict__ er,
                         const float* __restrict__ z8, const int* __restrict__ rowptr,
                         const int* __restrict__ csrc, const float* __restrict__ b,
                         float* __restrict__ out, int n)
{
    int w = (blockIdx.x * blockDim.x + threadIdx.x) >> 5;
    int lane = threadIdx.x & 31;
    if (w >= n) return;
    int beg = rowptr[w], end = rowptr[w + 1];
    float4 erv = ((const float4*)er)[w];
    float num[4][2] = {};
    float den[4] = {};
    for (int idx = beg + lane; idx < end; idx += 32) {
        int ss = csrc[idx];
        float4 l = ((const float4*)el)[ss];
        float e0 = l.x + erv.x, e1 = l.y + erv.y;
        float e2 = l.z + erv.z, e3 = l.w + erv.w;
        e0 = e0 > 0.f ? e0 : 0.2f * e0;
        e1 = e1 > 0.f ? e1 : 0.2f * e1;
        e2 = e2 > 0.f ? e2 : 0.2f * e2;
        e3 = e3 > 0.f ? e3 : 0.2f * e3;
        float a0 = __expf(e0), a1 = __expf(e1), a2 = __expf(e2), a3 = __expf(e3);
        den[0] += a0; den[1] += a1; den[2] += a2; den[3] += a3;
        float4 za = ((const float4*)z8)[(size_t)ss * 2];
        float4 zb = ((const float4*)z8)[(size_t)ss * 2 + 1];
        num[0][0] += a0 * za.x; num[0][1] += a0 * za.y;
        num[1][0] += a1 * za.z; num[1][1] += a1 * za.w;
        num[2][0] += a2 * zb.x; num[2][1] += a2 * zb.y;
        num[3][0] += a3 * zb.z; num[3][1] += a3 * zb.w;
    }
    #pragma unroll
    for (int off = 16; off; off >>= 1) {
        #pragma unroll
        for (int h = 0; h < 4; h++) {
            den[h]    += __shfl_xor_sync(0xffffffffu, den[h], off);
            num[h][0] += __shfl_xor_sync(0xffffffffu, num[h][0], off);
            num[h][1] += __shfl_xor_sync(0xffffffffu, num[h][1], off);
        }
    }
    if (lane == 0) {
        float4 l = ((const float4*)el)[w];
        float e0 = l.x + erv.x, e1 = l.y + erv.y;
        float e2 = l.z + erv.z, e3 = l.w + erv.w;
        e0 = e0 > 0.f ? e0 : 0.2f * e0;
        e1 = e1 > 0.f ? e1 : 0.2f * e1;
        e2 = e2 > 0.f ? e2 : 0.2f * e2;
        e3 = e3 > 0.f ? e3 : 0.2f * e3;
        float s0 = __expf(e0), s1 = __expf(e1), s2 = __expf(e2), s3 = __expf(e3);
        den[0] += s0; den[1] += s1; den[2] += s2; den[3] += s3;
        float4 za = ((const float4*)z8)[(size_t)w * 2];
        float4 zb = ((const float4*)z8)[(size_t)w * 2 + 1];
        num[0][0] += s0 * za.x; num[0][1] += s0 * za.y;
        num[1][0] += s1 * za.z; num[1][1] += s1 * za.w;
        num[2][0] += s2 * zb.x; num[2][1] += s2 * zb.y;
        num[3][0] += s3 * zb.z; num[3][1] += s3 * zb.w;
        float o0 = b[0] + b[2] + b[4] + b[6];
        float o1 = b[1] + b[3] + b[5] + b[7];
        o0 += num[0][0]/den[0] + num[1][0]/den[1] + num[2][0]/den[2] + num[3][0]/den[3];
        o1 += num[0][1]/den[0] + num[1][1]/den[1] + num[2][1]/den[2] + num[3][1]/den[3];
        ((float2*)out)[w] = make_float2(o0, o1);
    }
}

// ---------------- batchnorm stats ----------------
template<int SET>
__global__ void bn_stats(const float* __restrict__ h, int n)
{
    int t = threadIdx.x;
    int d = t & 63, rsub = t >> 6;
    float sum = 0.f, sq = 0.f;
    for (int row = blockIdx.x * 4 + rsub; row < n; row += gridDim.x * 4) {
        float v = h[(size_t)row * 64 + d];
        sum += v; sq += v * v;
    }
    __shared__ float sh[256], shq[256];
    sh[t] = sum; shq[t] = sq;
    __syncthreads();
    if (t < 64) {
        float s4 = sh[t] + sh[t + 64] + sh[t + 128] + sh[t + 192];
        float q4 = shq[t] + shq[t + 64] + shq[t + 128] + shq[t + 192];
        atomicAdd(&g_bnsum[SET][t], (double)s4);
        atomicAdd(&g_bnsq[SET][t], (double)q4);
    }
}

template<int SET>
__global__ void bn_final(const float* __restrict__ gamma, const float* __restrict__ beta, int n)
{
    int t = threadIdx.x;
    if (t >= 64) return;
    double mean = g_bnsum[SET][t] / n;
    double var  = g_bnsq[SET][t] / n - mean * mean;
    float sc = gamma[t] * rsqrtf((float)var + 1e-5f);
    g_scale[t] = sc;
    g_shift[t] = beta[t] - (float)mean * sc;
}

// ---------------- launch ----------------
extern "C" void kernel_launch(void* const* d_in, const int* in_sizes, int n_in,
                              void* d_out, int out_size)
{
    const float* feats = (const float*)d_in[0];
    const float* W1    = (const float*)d_in[1];
    const float* al1   = (const float*)d_in[2];
    const float* ar1   = (const float*)d_in[3];
    const float* b1    = (const float*)d_in[4];
    const float* Wm    = (const float*)d_in[5];
    const float* alm   = (const float*)d_in[6];
    const float* arm   = (const float*)d_in[7];
    const float* bm    = (const float*)d_in[8];
    const float* W2    = (const float*)d_in[9];
    const float* al2   = (const float*)d_in[10];
    const float* ar2   = (const float*)d_in[11];
    const float* b2    = (const float*)d_in[12];
    const float* gamma = (const float*)d_in[13];
    const float* beta  = (const float*)d_in[14];
    const int*   src   = (const int*)d_in[15];
    const int*   dst   = (const int*)d_in[16];
    float* out = (float*)d_out;

    int n = in_sizes[0] / 9;
    int E = in_sizes[15];

    void* p;
    float *z, *el, *er, *h;
    int *deg, *rowptr, *cursor, *csrc;
    cudaGetSymbolAddress(&p, g_z);      z      = (float*)p;
    cudaGetSymbolAddress(&p, g_el);     el     = (float*)p;
    cudaGetSymbolAddress(&p, g_er);     er     = (float*)p;
    cudaGetSymbolAddress(&p, g_h);      h      = (float*)p;
    cudaGetSymbolAddress(&p, g_deg);    deg    = (int*)p;
    cudaGetSymbolAddress(&p, g_rowptr); rowptr = (int*)p;
    cudaGetSymbolAddress(&p, g_cursor); cursor = (int*)p;
    cudaGetSymbolAddress(&p, g_csrc);   csrc   = (int*)p;
    __half2* zh = (__half2*)z;

    int gblk = (n + 31) / 32;   // gemm blocks (32 rows each)
    int ablk = (n + 7) / 8;     // aggregate blocks (8 warps each)
    int e4blk = (E / 4 + 256) / 256;

    // ---- CSR build (reused by all 3 layers) + zero BN accumulators ----
    zero_all<<<(n + 255) / 256, 256>>>(deg, n);
    count_deg<<<e4blk, 256>>>(dst, deg, E);
    scan_rowptr<<<1, 1024>>>(deg, rowptr, cursor, n);
    scatter_csr<<<e4blk, 256>>>(src, dst, cursor, csrc, E);

    // ---- Layer 1: feats[N,9] -> h[N,64] ----
    gemm_attn<9, false><<<gblk, 256>>>(feats, W1, al1, ar1, zh, el, er, n);
    gat_agg64<<<ablk, 256>>>(el, er, zh, rowptr, csrc, b1, h, n);
    bn_stats<0><<<128, 256>>>(h, n);
    bn_final<0><<<1, 64>>>(gamma, beta, n);

    // ---- Layer 2: bn(h) -> h[N,64]  (BN folded into gemm input load) ----
    gemm_attn<64, true><<<gblk, 256>>>(h, Wm, alm, arm, zh, el, er, n);
    gat_agg64<<<ablk, 256>>>(el, er, zh, rowptr, csrc, bm, h, n);
    bn_stats<1><<<128, 256>>>(h, n);
    bn_final<1><<<1, 64>>>(gamma, beta, n);

    // ---- Layer 3: bn(h) -> out[N,2] ----
    gemm8_attn<<<gblk, 256>>>(h, W2, al2, ar2, z, el, er, n);
    gat_agg2<<<ablk, 256>>>(el, er, z, rowptr, csrc, b2, out, n);
}

// round 14
// speedup vs baseline: 1.6126x; 1.0011x over previous
#include <cuda_runtime.h>
#include <cuda_bf16.h>
#include <cuda_fp16.h>

#define NN 50000
#define EE 800000

// ---------------- scratch (device globals; allocation-free) ----------------
// layers 1/2: z fp16 [N][H][D] contiguous per row (512B/row). layer 3: fp32 [N,8].
__device__ float  g_z [NN * 256];
__device__ float  g_el[NN * 4];
__device__ float  g_er[NN * 4];
__device__ float  g_h [NN * 64];          // layer activations (pre-BN)
__device__ int    g_deg[NN];
__device__ int    g_rowptr[NN + 1];
__device__ int    g_cursor[NN];
__device__ int    g_csrc[EE];             // CSR-by-dst: src ids
__device__ double g_bnsum[2][64], g_bnsq[2][64];   // double-buffered per layer
__device__ float  g_scale[64], g_shift[64];
__device__ float  g_bsum[2][64];          // head-summed biases (b1, bm)

// ---------------- packed f32x2 helpers (Blackwell) ----------------
__device__ __forceinline__ unsigned long long pack2(float lo, float hi) {
    unsigned long long d;
    asm("mov.b64 %0, {%1, %2};" : "=l"(d) : "f"(lo), "f"(hi));
    return d;
}
__device__ __forceinline__ void unpack2(unsigned long long d, float& lo, float& hi) {
    asm("mov.b64 {%0, %1}, %2;" : "=f"(lo), "=f"(hi) : "l"(d));
}
__device__ __forceinline__ void ffma2(unsigned long long& d, unsigned long long a,
                                      unsigned long long b) {
    asm("fma.rn.f32x2 %0, %1, %2, %0;" : "+l"(d) : "l"(a), "l"(b));
}

// ---------------- zero pass (deg + BN accumulators + head-summed biases) ----------------
__global__ void zero_all(int* deg, int n, const float* __restrict__ b1,
                         const float* __restrict__ bm)
{
    int i = blockIdx.x * blockDim.x + threadIdx.x;
    if (i < n) deg[i] = 0;
    if (blockIdx.x == 0 && threadIdx.x < 64) {
        int t = threadIdx.x;
        g_bnsum[0][t] = 0.0; g_bnsq[0][t] = 0.0;
        g_bnsum[1][t] = 0.0; g_bnsq[1][t] = 0.0;
        g_bsum[0][t] = b1[t] + b1[64 + t] + b1[128 + t] + b1[192 + t];
        g_bsum[1][t] = bm[t] + bm[64 + t] + bm[128 + t] + bm[192 + t];
    }
}

// ---------------- CSR build ----------------
__global__ void count_deg(const int* __restrict__ dst, int* __restrict__ deg, int E)
{
    int i0 = (blockIdx.x * blockDim.x + threadIdx.x) * 4;
    if (i0 + 3 < E) {
        int4 d4 = *(const int4*)(dst + i0);
        atomicAdd(&deg[d4.x], 1);
        atomicAdd(&deg[d4.y], 1);
        atomicAdd(&deg[d4.z], 1);
        atomicAdd(&deg[d4.w], 1);
    } else {
        for (int i = i0; i < E; i++) atomicAdd(&deg[dst[i]], 1);
    }
}

__global__ void scan_rowptr(const int* __restrict__ deg, int* __restrict__ rowptr,
                            int* __restrict__ cursor, int n)
{
    __shared__ int ts[1024];
    int t = threadIdx.x;
    int ch = (n + 1023) >> 10;
    int beg = t * ch;
    int end = beg + ch < n ? beg + ch : n;
    int s = 0;
    for (int i = beg; i < end; i++) s += deg[i];
    ts[t] = s;
    __syncthreads();
    for (int off = 1; off < 1024; off <<= 1) {
        int v = (t >= off) ? ts[t - off] : 0;
        __syncthreads();
        ts[t] += v;
        __syncthreads();
    }
    int run = ts[t] - s;   // exclusive prefix
    for (int i = beg; i < end; i++) {
        rowptr[i] = run; cursor[i] = run; run += deg[i];
    }
    if (t == 1023) rowptr[n] = ts[1023];
}

__global__ void scatter_csr(const int* __restrict__ src, const int* __restrict__ dst,
                            int* __restrict__ cursor, int* __restrict__ csrc, int E)
{
    int i0 = (blockIdx.x * blockDim.x + threadIdx.x) * 4;
    if (i0 + 3 < E) {
        int4 d4 = *(const int4*)(dst + i0);
        int4 s4 = *(const int4*)(src + i0);
        int p0 = atomicAdd(&cursor[d4.x], 1);
        int p1 = atomicAdd(&cursor[d4.y], 1);
        int p2 = atomicAdd(&cursor[d4.z], 1);
        int p3 = atomicAdd(&cursor[d4.w], 1);
        csrc[p0] = s4.x; csrc[p1] = s4.y; csrc[p2] = s4.z; csrc[p3] = s4.w;
    } else {
        for (int i = i0; i < E; i++) {
            int pos = atomicAdd(&cursor[dst[i]], 1);
            csrc[pos] = src[i];
        }
    }
}

// ---------------- GEMM (Nout=256, fp16 z out) + fused el/er, optional fused BN ----------------
// block = 256 threads, 32 rows/block; thread t: cols 4*(t&63), rows (t>>6)*8 .. +7 (4 pairs)
template<int KIN, bool APPLY_BN>
__global__ void gemm_attn(const float* __restrict__ x, const float* __restrict__ W,
                          const float* __restrict__ al, const float* __restrict__ ar,
                          __half2* __restrict__ z, float* __restrict__ el,
                          float* __restrict__ er, int n)
{
    __shared__ __align__(16) float xs[KIN][34];   // k-major; pad 34 (even) for banks+align
    int t = threadIdx.x;
    int base = blockIdx.x * 32;
    for (int idx = t; idx < 32 * KIN; idx += 256) {
        int r = idx / KIN, k = idx - r * KIN;     // coalesced read along k
        int row = base + r;
        float v = (row < n) ? x[(size_t)row * KIN + k] : 0.f;
        if (APPLY_BN) v = v * g_scale[k] + g_shift[k];
        xs[k][r] = v;
    }
    __syncthreads();
    int c4 = t & 63, rr = t >> 6;
    const float4* W4 = (const float4*)W;
    unsigned long long acc[4][4];
    #pragma unroll
    for (int rp = 0; rp < 4; rp++)
        #pragma unroll
        for (int c = 0; c < 4; c++) acc[rp][c] = 0ull;
    for (int k = 0; k < KIN; k++) {
        float4 w = W4[k * 64 + c4];
        unsigned long long wd0 = pack2(w.x, w.x), wd1 = pack2(w.y, w.y),
                           wd2 = pack2(w.z, w.z), wd3 = pack2(w.w, w.w);
        const unsigned long long* xp = (const unsigned long long*)(&xs[k][rr * 8]);
        #pragma unroll
        for (int rp = 0; rp < 4; rp++) {
            unsigned long long xv = xp[rp];       // rows (rr*8+2rp, +1) packed
            ffma2(acc[rp][0], xv, wd0);
            ffma2(acc[rp][1], xv, wd1);
            ffma2(acc[rp][2], xv, wd2);
            ffma2(acc[rp][3], xv, wd3);
        }
    }
    float4 alv = ((const float4*)al)[c4];
    float4 arv = ((const float4*)ar)[c4];
    #pragma unroll
    for (int rp = 0; rp < 4; rp++) {
        float v0[4], v1[4];
        unpack2(acc[rp][0], v0[0], v1[0]);
        unpack2(acc[rp][1], v0[1], v1[1]);
        unpack2(acc[rp][2], v0[2], v1[2]);
        unpack2(acc[rp][3], v0[3], v1[3]);
        #pragma unroll
        for (int half = 0; half < 2; half++) {
            float* vv = half ? v1 : v0;
            int row = base + rr * 8 + rp * 2 + half;
            if (row < n) {
                __half2 ha = __floats2half2_rn(vv[0], vv[1]);
                __half2 hb = __floats2half2_rn(vv[2], vv[3]);
                __half2* zp = z + (size_t)row * 128 + c4 * 2;   // coalesced 8B/thread
                zp[0] = ha; zp[1] = hb;
            }
            float p = vv[0]*alv.x + vv[1]*alv.y + vv[2]*alv.z + vv[3]*alv.w;
            float q = vv[0]*arv.x + vv[1]*arv.y + vv[2]*arv.z + vv[3]*arv.w;
            #pragma unroll
            for (int off = 8; off; off >>= 1) {
                p += __shfl_xor_sync(0xffffffffu, p, off);
                q += __shfl_xor_sync(0xffffffffu, q, off);
            }
            if ((c4 & 15) == 0 && row < n) {
                el[row * 4 + (c4 >> 4)] = p;
                er[row * 4 + (c4 >> 4)] = q;
            }
        }
    }
}

// ---------------- GEMM (Nout=8, layer 3, fp32 z) + fused el/er + fused BN ----------------
__global__ void gemm8_attn(const float* __restrict__ x, const float* __restrict__ W,
                           const float* __restrict__ al, const float* __restrict__ ar,
                           float* __restrict__ z, float* __restrict__ el,
                           float* __restrict__ er, int n)
{
    __shared__ float xs[32][64];
    __shared__ float ws[512];
    int t = threadIdx.x;
    int base = blockIdx.x * 32;
    for (int idx = t; idx < 512; idx += 256) ws[idx] = W[idx];
    for (int idx = t; idx < 2048; idx += 256) {
        int r = idx >> 6, k = idx & 63;
        int row = base + r;
        float v = (row < n) ? x[(size_t)row * 64 + k] : 0.f;
        xs[r][k] = v * g_scale[k] + g_shift[k];
    }
    __syncthreads();
    int nl = t >> 3, j = t & 7;
    int row = base + nl;
    float acc = 0.f;
    #pragma unroll
    for (int k = 0; k < 64; k++) acc += xs[nl][k] * ws[k * 8 + j];
    float p = acc * al[j], q = acc * ar[j];
    float p2 = p + __shfl_xor_sync(0xffffffffu, p, 1);
    float q2 = q + __shfl_xor_sync(0xffffffffu, q, 1);
    if (row < n) {
        z[(size_t)row * 8 + j] = acc;
        if ((j & 1) == 0) { el[row * 4 + (j >> 1)] = p2; er[row * 4 + (j >> 1)] = q2; }
    }
}

// ---------------- fused GAT aggregate (D=64, fp16 z): warp per dst node ----------------
// lane mapping: head = lane>>3, dims = (lane&7)*8 .. +7  -> ONE LDG.128 per edge
__global__ void gat_agg64(const float* __restrict__ el, const float* __restrict__ er,
                          const uint4* __restrict__ z, const int* __restrict__ rowptr,
                          const int* __restrict__ csrc, const float* __restrict__ bsum,
                          float* __restrict__ out, int n)
{
    __shared__ __align__(16) float4 sa[8][32];
    __shared__ int sid[8][32];
    int w = (blockIdx.x * blockDim.x + threadIdx.x) >> 5;
    int wslot = (threadIdx.x >> 5) & 7;
    int lane = threadIdx.x & 31;
    if (w >= n) return;
    int beg = rowptr[w], end = rowptr[w + 1];
    float4 erv = ((const float4*)er)[w];
    float num[8] = {};
    float den[4] = {};
    int hsel = lane >> 3;
    for (int c = beg; c < end; c += 32) {
        int idx = c + lane;
        float a0 = 0.f, a1 = 0.f, a2 = 0.f, a3 = 0.f;
        int ss = 0;
        if (idx < end) {
            ss = csrc[idx];
            float4 l = ((const float4*)el)[ss];
            float e0 = l.x + erv.x, e1 = l.y + erv.y;
            float e2 = l.z + erv.z, e3 = l.w + erv.w;
            e0 = e0 > 0.f ? e0 : 0.2f * e0;
            e1 = e1 > 0.f ? e1 : 0.2f * e1;
            e2 = e2 > 0.f ? e2 : 0.2f * e2;
            e3 = e3 > 0.f ? e3 : 0.2f * e3;
            a0 = __expf(e0); a1 = __expf(e1); a2 = __expf(e2); a3 = __expf(e3);
            den[0] += a0; den[1] += a1; den[2] += a2; den[3] += a3;
        }
        sa[wslot][lane] = make_float4(a0, a1, a2, a3);
        sid[wslot][lane] = ss;
        __syncwarp();
        int m = end - c; if (m > 32) m = 32;
        #pragma unroll 4
        for (int j = 0; j < m; j++) {
            float av = ((const float*)&sa[wslot][j])[hsel];   // LDS.32, 4 banks, bcast
            int    sj = sid[wslot][j];                        // LDS.32 broadcast
            uint4 qv = z[(size_t)sj * 32 + lane];             // ONE LDG.128: 8 dims of head hsel
            float2 f0 = __half22float2(*(__half2*)&qv.x);
            float2 f1 = __half22float2(*(__half2*)&qv.y);
            float2 f2 = __half22float2(*(__half2*)&qv.z);
            float2 f3 = __half22float2(*(__half2*)&qv.w);
            num[0] += av * f0.x; num[1] += av * f0.y;
            num[2] += av * f1.x; num[3] += av * f1.y;
            num[4] += av * f2.x; num[5] += av * f2.y;
            num[6] += av * f3.x; num[7] += av * f3.y;
        }
        __syncwarp();
    }
    // warp-reduce denominators (all lanes end with full sums)
    #pragma unroll
    for (int off = 16; off; off >>= 1) {
        den[0] += __shfl_xor_sync(0xffffffffu, den[0], off);
        den[1] += __shfl_xor_sync(0xffffffffu, den[1], off);
        den[2] += __shfl_xor_sync(0xffffffffu, den[2], off);
        den[3] += __shfl_xor_sync(0xffffffffu, den[3], off);
    }
    // self-loop
    {
        float4 l = ((const float4*)el)[w];
        float e0 = l.x + erv.x, e1 = l.y + erv.y;
        float e2 = l.z + erv.z, e3 = l.w + erv.w;
        e0 = e0 > 0.f ? e0 : 0.2f * e0;
        e1 = e1 > 0.f ? e1 : 0.2f * e1;
        e2 = e2 > 0.f ? e2 : 0.2f * e2;
        e3 = e3 > 0.f ? e3 : 0.2f * e3;
        float s0 = __expf(e0), s1 = __expf(e1), s2 = __expf(e2), s3 = __expf(e3);
        den[0] += s0; den[1] += s1; den[2] += s2; den[3] += s3;
        float sv = (lane & 16) ? ((lane & 8) ? s3 : s2) : ((lane & 8) ? s1 : s0);
        uint4 qv = z[(size_t)w * 32 + lane];
        float2 f0 = __half22float2(*(__half2*)&qv.x);
        float2 f1 = __half22float2(*(__half2*)&qv.y);
        float2 f2 = __half22float2(*(__half2*)&qv.z);
        float2 f3 = __half22float2(*(__half2*)&qv.w);
        num[0] += sv * f0.x; num[1] += sv * f0.y;
        num[2] += sv * f1.x; num[3] += sv * f1.y;
        num[4] += sv * f2.x; num[5] += sv * f2.y;
        num[6] += sv * f3.x; num[7] += sv * f3.y;
    }
    // scale by this lane's head denominator (SEL chain, no dynamic reg index)
    float dsel = (lane & 16) ? ((lane & 8) ? den[3] : den[2])
                             : ((lane & 8) ? den[1] : den[0]);
    float rr = __fdividef(1.f, dsel);
    #pragma unroll
    for (int u = 0; u < 8; u++) num[u] *= rr;
    // head-sum: combine lanes {l, l+8, l+16, l+24}
    #pragma unroll
    for (int u = 0; u < 8; u++) {
        num[u] += __shfl_xor_sync(0xffffffffu, num[u], 8);
        num[u] += __shfl_xor_sync(0xffffffffu, num[u], 16);
    }
    if (lane < 8) {
        const float4* bs = (const float4*)(bsum + lane * 8);
        float4 ba = bs[0], bb = bs[1];
        float4 o0 = make_float4(num[0] + ba.x, num[1] + ba.y, num[2] + ba.z, num[3] + ba.w);
        float4 o1 = make_float4(num[4] + bb.x, num[5] + bb.y, num[6] + bb.z, num[7] + bb.w);
        float4* op = (float4*)(out + (size_t)w * 64 + lane * 8);
        op[0] = o0; op[1] = o1;
    }
}

// ---------------- fused GAT aggregate (C=2, layer 3, fp32 z): warp per dst node ----------------
__global__ void gat_agg2(const float* __restrict__ el, const float* __restrict__ er,
                         const float* __restrict__ z8, const int* __restrict__ rowptr,
                         const int* __restrict__ csrc, const float* __restrict__ b,
                         float* __restrict__ out, int n)
{
    int w = (blockIdx.x * blockDim.x + threadIdx.x) >> 5;
    int lane = threadIdx.x & 31;
    if (w >= n) return;
    int beg = rowptr[w], end = rowptr[w + 1];
    float4 erv = ((const float4*)er)[w];
    float num[4][2] = {};
    float den[4] = {};
    for (int idx = beg + lane; idx < end; idx += 32) {
        int ss = csrc[idx];
        float4 l = ((const float4*)el)[ss];
        float e0 = l.x + erv.x, e1 = l.y + erv.y;
        float e2 = l.z + erv.z, e3 = l.w + erv.w;
        e0 = e0 > 0.f ? e0 : 0.2f * e0;
        e1 = e1 > 0.f ? e1 : 0.2f * e1;
        e2 = e2 > 0.f ? e2 : 0.2f * e2;
        e3 = e3 > 0.f ? e3 : 0.2f * e3;
        float a0 = __expf(e0), a1 = __expf(e1), a2 = __expf(e2), a3 = __expf(e3);
        den[0] += a0; den[1] += a1; den[2] += a2; den[3] += a3;
        float4 za = ((const float4*)z8)[(size_t)ss * 2];
        float4 zb = ((const float4*)z8)[(size_t)ss * 2 + 1];
        num[0][0] += a0 * za.x; num[0][1] += a0 * za.y;
        num[1][0] += a1 * za.z; num[1][1] += a1 * za.w;
        num[2][0] += a2 * zb.x; num[2][1] += a2 * zb.y;
        num[3][0] += a3 * zb.z; num[3][1] += a3 * zb.w;
    }
    #pragma unroll
    for (int off = 16; off; off >>= 1) {
        #pragma unroll
        for (int h = 0; h < 4; h++) {
            den[h]    += __shfl_xor_sync(0xffffffffu, den[h], off);
            num[h][0] += __shfl_xor_sync(0xffffffffu, num[h][0], off);
            num[h][1] += __shfl_xor_sync(0xffffffffu, num[h][1], off);
        }
    }
    if (lane == 0) {
        float4 l = ((const float4*)el)[w];
        float e0 = l.x + erv.x, e1 = l.y + erv.y;
        float e2 = l.z + erv.z, e3 = l.w + erv.w;
        e0 = e0 > 0.f ? e0 : 0.2f * e0;
        e1 = e1 > 0.f ? e1 : 0.2f * e1;
        e2 = e2 > 0.f ? e2 : 0.2f * e2;
        e3 = e3 > 0.f ? e3 : 0.2f * e3;
        float s0 = __expf(e0), s1 = __expf(e1), s2 = __expf(e2), s3 = __expf(e3);
        den[0] += s0; den[1] += s1; den[2] += s2; den[3] += s3;
        float4 za = ((const float4*)z8)[(size_t)w * 2];
        float4 zb = ((const float4*)z8)[(size_t)w * 2 + 1];
        num[0][0] += s0 * za.x; num[0][1] += s0 * za.y;
        num[1][0] += s1 * za.z; num[1][1] += s1 * za.w;
        num[2][0] += s2 * zb.x; num[2][1] += s2 * zb.y;
        num[3][0] += s3 * zb.z; num[3][1] += s3 * zb.w;
        float o0 = b[0] + b[2] + b[4] + b[6];
        float o1 = b[1] + b[3] + b[5] + b[7];
        o0 += num[0][0]/den[0] + num[1][0]/den[1] + num[2][0]/den[2] + num[3][0]/den[3];
        o1 += num[0][1]/den[0] + num[1][1]/den[1] + num[2][1]/den[2] + num[3][1]/den[3];
        ((float2*)out)[w] = make_float2(o0, o1);
    }
}

// ---------------- batchnorm stats ----------------
template<int SET>
__global__ void bn_stats(const float* __restrict__ h, int n)
{
    int t = threadIdx.x;
    int d = t & 63, rsub = t >> 6;
    float sum = 0.f, sq = 0.f;
    for (int row = blockIdx.x * 4 + rsub; row < n; row += gridDim.x * 4) {
        float v = h[(size_t)row * 64 + d];
        sum += v; sq += v * v;
    }
    __shared__ float sh[256], shq[256];
    sh[t] = sum; shq[t] = sq;
    __syncthreads();
    if (t < 64) {
        float s4 = sh[t] + sh[t + 64] + sh[t + 128] + sh[t + 192];
        float q4 = shq[t] + shq[t + 64] + shq[t + 128] + shq[t + 192];
        atomicAdd(&g_bnsum[SET][t], (double)s4);
        atomicAdd(&g_bnsq[SET][t], (double)q4);
    }
}

template<int SET>
__global__ void bn_final(const float* __restrict__ gamma, const float* __restrict__ beta, int n)
{
    int t = threadIdx.x;
    if (t >= 64) return;
    double mean = g_bnsum[SET][t] / n;
    double var  = g_bnsq[SET][t] / n - mean * mean;
    float sc = gamma[t] * rsqrtf((float)var + 1e-5f);
    g_scale[t] = sc;
    g_shift[t] = beta[t] - (float)mean * sc;
}

// ---------------- launch ----------------
extern "C" void kernel_launch(void* const* d_in, const int* in_sizes, int n_in,
                              void* d_out, int out_size)
{
    const float* feats = (const float*)d_in[0];
    const float* W1    = (const float*)d_in[1];
    const float* al1   = (const float*)d_in[2];
    const float* ar1   = (const float*)d_in[3];
    const float* b1    = (const float*)d_in[4];
    const float* Wm    = (const float*)d_in[5];
    const float* alm   = (const float*)d_in[6];
    const float* arm   = (const float*)d_in[7];
    const float* bm    = (const float*)d_in[8];
    const float* W2    = (const float*)d_in[9];
    const float* al2   = (const float*)d_in[10];
    const float* ar2   = (const float*)d_in[11];
    const float* b2    = (const float*)d_in[12];
    const float* gamma = (const float*)d_in[13];
    const float* beta  = (const float*)d_in[14];
    const int*   src   = (const int*)d_in[15];
    const int*   dst   = (const int*)d_in[16];
    float* out = (float*)d_out;

    int n = in_sizes[0] / 9;
    int E = in_sizes[15];

    void* p;
    float *z, *el, *er, *h, *bsum;
    int *deg, *rowptr, *cursor, *csrc;
    cudaGetSymbolAddress(&p, g_z);      z      = (float*)p;
    cudaGetSymbolAddress(&p, g_el);     el     = (float*)p;
    cudaGetSymbolAddress(&p, g_er);     er     = (float*)p;
    cudaGetSymbolAddress(&p, g_h);      h      = (float*)p;
    cudaGetSymbolAddress(&p, g_deg);    deg    = (int*)p;
    cudaGetSymbolAddress(&p, g_rowptr); rowptr = (int*)p;
    cudaGetSymbolAddress(&p, g_cursor); cursor = (int*)p;
    cudaGetSymbolAddress(&p, g_csrc);   csrc   = (int*)p;
    cudaGetSymbolAddress(&p, g_bsum);   bsum   = (float*)p;
    __half2* zh = (__half2*)z;
    uint4* z4 = (uint4*)z;

    int gblk = (n + 31) / 32;   // gemm blocks (32 rows each)
    int ablk = (n + 7) / 8;     // aggregate blocks (8 warps each)
    int e4blk = (E / 4 + 256) / 256;

    // ---- CSR build (reused by all 3 layers) + zero BN accumulators + bias sums ----
    zero_all<<<(n + 255) / 256, 256>>>(deg, n, b1, bm);
    count_deg<<<e4blk, 256>>>(dst, deg, E);
    scan_rowptr<<<1, 1024>>>(deg, rowptr, cursor, n);
    scatter_csr<<<e4blk, 256>>>(src, dst, cursor, csrc, E);

    // ---- Layer 1: feats[N,9] -> h[N,64] ----
    gemm_attn<9, false><<<gblk, 256>>>(feats, W1, al1, ar1, zh, el, er, n);
    gat_agg64<<<ablk, 256>>>(el, er, z4, rowptr, csrc, bsum, h, n);
    bn_stats<0><<<128, 256>>>(h, n);
    bn_final<0><<<1, 64>>>(gamma, beta, n);

    // ---- Layer 2: bn(h) -> h[N,64]  (BN folded into gemm input load) ----
    gemm_attn<64, true><<<gblk, 256>>>(h, Wm, alm, arm, zh, el, er, n);
    gat_agg64<<<ablk, 256>>>(el, er, z4, rowptr, csrc, bsum + 64, h, n);
    bn_stats<1><<<128, 256>>>(h, n);
    bn_final<1><<<1, 64>>>(gamma, beta, n);

    // ---- Layer 3: bn(h) -> out[N,2] ----
    gemm8_attn<<<gblk, 256>>>(h, W2, al2, ar2, z, el, er, n);
    gat_agg2<<<ablk, 256>>>(el, er, z, rowptr, csrc, b2, out, n);
}